// round 16
// baseline (speedup 1.0000x reference)
#include <cuda_runtime.h>
#include <cuda_fp16.h>
#include <cstdint>
#include <math.h>

// LayerGate as one GEMM D[65536,512] = X[65536,512] @ W_aug[512,512] (per j-block),
// fp16 single-pass mma.sync.m16n8k16 (fp32 acc), fused gate epilogue.
// A fragments pre-packed in MMA register order -> loaded register-direct via LDG.128
// (no A smem round trip). B via 3-stage cp.async (K=128/stage, 4 barriers total).
// 2 CTAs/SM (<=128 regs). Weight columns reordered n' = h*4 + g.

namespace {
constexpr int STAGE_BYTES = 32768;   // per stage: B only, K=128 slice (128 n' x 128 k)
constexpr int NSTAGE      = 3;
constexpr int SMEM_TOTAL  = 98304;   // 3 stages (front 64KB reused as gate tile)
}

// A fragment planes: [rowblk][kblk 8][lane 32][16B], 16B = one thread's a0..a3
__device__ __align__(16) unsigned char g_fa0[4096ull * 8 * 32 * 16]; // CNN (rows 65536)
__device__ __align__(16) unsigned char g_fgf[1024ull * 8 * 32 * 16]; // gaz  (rows 16384)
__device__ __align__(16) unsigned char g_fgb[1024ull * 8 * 32 * 16]; // gazb
__device__ __align__(16) unsigned char g_fgm[1024ull * 8 * 32 * 16]; // gm
__device__ __align__(16) unsigned char g_fex[1024ull * 8 * 32 * 16]; // exp
// [j][n'][k] fp16, n'=512 reordered cols = 2MB
__device__ __align__(16) unsigned char g_wh[4ull * 512 * 1024];

// ---------- PTX helpers (compute_80-level; safe under .target sm_103) ----------
__device__ __forceinline__ uint32_t smem_u32(const void* p) {
    uint32_t a;
    asm("{ .reg .u64 t; cvta.to.shared.u64 t, %1; cvt.u32.u64 %0, t; }" : "=r"(a) : "l"(p));
    return a;
}
__device__ __forceinline__ void cp16(uint32_t dst, const void* src) {
    asm volatile("cp.async.cg.shared.global [%0], [%1], 16;" :: "r"(dst), "l"(src));
}
__device__ __forceinline__ void cp_commit() {
    asm volatile("cp.async.commit_group;" ::: "memory");
}
__device__ __forceinline__ void cp_wait1() {
    asm volatile("cp.async.wait_group 1;" ::: "memory");
}
__device__ __forceinline__ void ldsm4(uint32_t* r, uint32_t addr) {
    asm volatile("ldmatrix.sync.aligned.m8n8.x4.shared.b16 {%0,%1,%2,%3}, [%4];"
                 : "=r"(r[0]), "=r"(r[1]), "=r"(r[2]), "=r"(r[3]) : "r"(addr));
}
__device__ __forceinline__ void mma_fp16(float* d, const uint32_t* a, const uint32_t* b) {
    asm volatile("mma.sync.aligned.m16n8k16.row.col.f32.f16.f16.f32 "
                 "{%0,%1,%2,%3}, {%4,%5,%6,%7}, {%8,%9}, {%0,%1,%2,%3};"
                 : "+f"(d[0]), "+f"(d[1]), "+f"(d[2]), "+f"(d[3])
                 : "r"(a[0]), "r"(a[1]), "r"(a[2]), "r"(a[3]), "r"(b[0]), "r"(b[1]));
}
__device__ __forceinline__ uint32_t h2u(__half2 h) { return *reinterpret_cast<uint32_t*>(&h); }

// ---------- Prep: A fragment planes + weights, one launch ----------
// blocks [0,8192): A fragments (CNN then gaz/gazb/gm/exp); [8192,9216): weights
__global__ void __launch_bounds__(256) wprep(const float* __restrict__ cnn,
                                             const float* __restrict__ gaz,
                                             const float* __restrict__ gazb,
                                             const float* __restrict__ gm,
                                             const float* __restrict__ expi,
                                             const float* __restrict__ Wcat,
                                             const float* __restrict__ Wexp)
{
    const int bx = blockIdx.x;
    if (bx < 8192) {
        int idx = bx * 256 + threadIdx.x;          // 2,097,152 fragment-16B writers
        int lane = idx & 31;
        int kblk = (idx >> 5) & 7;
        const float* srcrow0;                      // fp32 row r0 base (stride 128 floats)
        unsigned char* dstp;
        if (idx < 1048576) {                       // CNN: 4096 rowblks
            int rowblk = idx >> 8;
            int r0 = rowblk * 16 + (lane >> 2);
            int j = r0 >> 14, b = (r0 >> 9) & 31, s = r0 & 511;
            srcrow0 = cnn + ((size_t)(b * 2048 + j * 512 + s) << 7);
            dstp = g_fa0 + ((size_t)(rowblk * 8 + kblk) * 32 + lane) * 16;
        } else {                                   // shared planes: 1024 rowblks each
            int idx2 = idx - 1048576;
            int p = idx2 >> 18;
            int rowblk = (idx2 & 262143) >> 8;
            int rr0 = rowblk * 16 + (lane >> 2);
            const float* base = (p == 0) ? gaz : (p == 1) ? gazb : (p == 2) ? gm : expi;
            unsigned char* pl  = (p == 0) ? g_fgf : (p == 1) ? g_fgb : (p == 2) ? g_fgm : g_fex;
            srcrow0 = base + ((size_t)rr0 << 7);
            dstp = pl + ((size_t)(rowblk * 8 + kblk) * 32 + lane) * 16;
        }
        int c0 = kblk * 16 + 2 * (lane & 3);
        float2 v00 = *reinterpret_cast<const float2*>(srcrow0 + c0);            // (r0,   c0)
        float2 v10 = *reinterpret_cast<const float2*>(srcrow0 + (8 << 7) + c0); // (r0+8, c0)
        float2 v01 = *reinterpret_cast<const float2*>(srcrow0 + c0 + 8);        // (r0,   c0+8)
        float2 v11 = *reinterpret_cast<const float2*>(srcrow0 + (8 << 7) + c0 + 8);
        uint4 o = make_uint4(h2u(__floats2half2_rn(v00.x, v00.y)),   // a0
                             h2u(__floats2half2_rn(v10.x, v10.y)),   // a1
                             h2u(__floats2half2_rn(v01.x, v01.y)),   // a2
                             h2u(__floats2half2_rn(v11.x, v11.y)));  // a3
        *reinterpret_cast<uint4*>(dstp) = o;
    } else {
        // weights -> g_wh, columns reordered n' = h*4+g
        int idx = (bx - 8192) * 256 + threadIdx.x;
        int h = idx & 127;
        int k = (idx >> 7) & 511;
        int j = idx >> 16;
#pragma unroll
        for (int g = 0; g < 4; g++) {
            float v;
            if (k < 384)     v = Wcat[(size_t)k * 2048 + j * 512 + g * 128 + h];
            else if (g >= 1) v = Wexp[(size_t)(k - 384) * 1536 + j * 384 + (g - 1) * 128 + h];
            else             v = 0.f;
            int npr = h * 4 + g;
            *reinterpret_cast<__half*>(g_wh + ((size_t)(j * 512) + npr) * 1024 + k * 2) =
                __float2half_rn(v);
        }
    }
}

// ---------- Main: register-direct A + 3-stage B pipeline + fused epilogue ----------
__global__ void __launch_bounds__(256, 2)
layergate_mma(const float* __restrict__ cnn,
              const float* __restrict__ expi,
              const float* __restrict__ bcat,
              const float* __restrict__ bexp,
              float* __restrict__ out)
{
    extern __shared__ __align__(1024) unsigned char smem[];
    const uint32_t sbase = smem_u32(smem);
    const int tid  = threadIdx.x;
    const int lane = tid & 31;
    const int wid  = tid >> 5;
    const int wm   = wid & 3;     // 4 warps in M (32 rows each)
    const int wn   = wid >> 2;    // 2 warps in N (64 cols each)
    const int nt   = blockIdx.x;  // 0..3   (h-block of 32)
    const int mx   = blockIdx.y;  // 0..127 (128-row tile within j)
    const int j    = blockIdx.z;  // 0..3
    const int rbase = j * 16384 + mx * 128;
    const int b    = mx >> 2;           // batch of this tile
    const int s0   = (mx & 3) * 128;    // sequence offset of row 0

    // A fragment base pointers per k-chunk sel (this thread's wm & lane baked in)
    const unsigned char* fbase[4];
    {
        int rb0 = (rbase >> 4) + wm * 2;
        fbase[0] = g_fa0 + ((size_t)(rb0 * 8) * 32 + lane) * 16;
        int rs0 = ((b * 512 + s0) >> 4) + wm * 2;
        size_t off = ((size_t)(rs0 * 8) * 32 + lane) * 16;
        fbase[1] = ((j & 1) ? g_fgb : g_fgf) + off;
        fbase[2] = g_fgm + off;
        fbase[3] = g_fex + off;
    }

    float acc[2][8][4];
#pragma unroll
    for (int mf = 0; mf < 2; mf++)
#pragma unroll
        for (int nf = 0; nf < 8; nf++)
#pragma unroll
            for (int c = 0; c < 4; c++) acc[mf][nf][c] = 0.f;

    uint32_t Ar[3][2][4];   // A fragment ring (3 kb deep)
    auto ldgA = [&](int kb, int slot) {
        const unsigned char* p = fbase[kb >> 3] + (kb & 7) * 512;
#pragma unroll
        for (int mf = 0; mf < 2; mf++) {
            uint4 v = *reinterpret_cast<const uint4*>(p + mf * 4096);
            Ar[slot][mf][0] = v.x; Ar[slot][mf][1] = v.y;
            Ar[slot][mf][2] = v.z; Ar[slot][mf][3] = v.w;
        }
    };

    // ---- B stage loader: 2048 chunks (2 x 16KB subtiles), 8 cp16/thread
    auto issue_stage = [&](int s) {
        const uint32_t dst = sbase + (s % NSTAGE) * STAGE_BYTES;
#pragma unroll
        for (int i = 0; i < 8; i++) {
            int c = i * 256 + tid;
            int sub = c >> 10;
            int r = (c & 1023) >> 3, ch = c & 7;
            const unsigned char* src =
                g_wh + ((size_t)(j * 512) + nt * 128 + r) * 1024 + (s * 2 + sub) * 128 + ch * 16;
            cp16(dst + sub * 16384 + r * 128 + ((ch ^ (r & 7)) * 16), src);
        }
        cp_commit();
    };

    // ldmatrix lane geometry (B only)
    const int brow = (lane & 7) | ((lane >> 4) << 3);
    const int bc   = (lane >> 3) & 1;

    ldgA(0, 0); ldgA(1, 1); ldgA(2, 2);
    issue_stage(0);
    issue_stage(1);

#pragma unroll
    for (int s = 0; s < 4; s++) {
        cp_wait1();                      // B stage s landed (s+1 may still fly)
        __syncthreads();                 // all warps past stage s-1 compute
        if (s + 2 < 4) issue_stage(s + 2);
        else           cp_commit();      // empty group keeps wait arithmetic exact
        const uint32_t st = sbase + (s % NSTAGE) * STAGE_BYTES;
        const uint32_t bRow = st + (wn * 64 + brow) * 128;
#pragma unroll
        for (int kbl = 0; kbl < 8; kbl++) {
            const int kb = s * 8 + kbl;
            const int slot = kb % 3;
            const uint32_t bBase = bRow + (kbl >> 2) * 16384;
            const uint32_t boff = ((((kbl & 3) * 2) + bc) ^ (brow & 7)) * 16;
            uint32_t B[8][2];
#pragma unroll
            for (int ng = 0; ng < 4; ng++) {
                uint32_t t[4];
                ldsm4(t, bBase + ng * 2048 + boff);
                B[2 * ng][0] = t[0]; B[2 * ng][1] = t[1];
                B[2 * ng + 1][0] = t[2]; B[2 * ng + 1][1] = t[3];
            }
#pragma unroll
            for (int mf = 0; mf < 2; mf++)
#pragma unroll
                for (int nf = 0; nf < 8; nf++)
                    mma_fp16(acc[mf][nf], Ar[slot][mf], B[nf]);
            if (kb + 3 < 32) ldgA(kb + 3, slot);   // refill ring slot just freed
        }
    }

    // ---- Epilogue phase 1: dump acc to smem gate tile [128 rows][128 n'] fp32
    __syncthreads();
    float* gate = reinterpret_cast<float*>(smem);
    const int gid = lane >> 2, tig = lane & 3;
#pragma unroll
    for (int mf = 0; mf < 2; mf++)
#pragma unroll
        for (int nf = 0; nf < 8; nf++) {
            int row = wm * 32 + mf * 16 + gid;
            int col = wn * 64 + nf * 8 + tig * 2;
            *reinterpret_cast<float2*>(gate + row * 128 + col) =
                make_float2(acc[mf][nf][0], acc[mf][nf][1]);
            *reinterpret_cast<float2*>(gate + (row + 8) * 128 + col) =
                make_float2(acc[mf][nf][2], acc[mf][nf][3]);
        }
    __syncthreads();

    // ---- Epilogue phase 2: per (row, h) gather float4 {ns,g1,g2,g3}, finish, store
    const int hl = lane;
    const int hg = nt * 32 + hl;
    const float bc0 = bcat[j * 512 + hg];
    const float bc1 = bcat[j * 512 + 128 + hg];
    const float bc2 = bcat[j * 512 + 256 + hg];
    const float bc3 = bcat[j * 512 + 384 + hg];
    const float be1 = bexp[j * 384 + hg];
    const float be2 = bexp[j * 384 + 128 + hg];
    const float be3 = bexp[j * 384 + 256 + hg];
#pragma unroll
    for (int i = 0; i < 16; i++) {
        const int row = wid * 16 + i;
        const int srow = s0 + row;
        float4 gv = *reinterpret_cast<const float4*>(gate + row * 128 + hl * 4);
        float s1 = cnn[((size_t)(b * 2048 + j * 512 + srow) << 7) + hg];
        float s2 = expi[((size_t)(b * 512 + srow) << 7) + hg];
        float ns = tanhf(gv.x + bc0);
        float g1 = 1.f / (1.f + __expf(-(gv.y + bc1 + be1)));
        float g2 = 1.f / (1.f + __expf(-(gv.z + bc2 + be2)));
        float g3 = 1.f / (1.f + __expf(-(gv.w + bc3 + be3)));
        float e1 = __expf(g1), e2 = __expf(g2), e3 = __expf(g3);
        float inv = 1.f / (e1 + e2 + e3);
        out[((size_t)(rbase + row) << 7) + hg] = (e1 * ns + e2 * s1 + e3 * s2) * inv;
    }
}

extern "C" void kernel_launch(void* const* d_in, const int* in_sizes, int n_in,
                              void* d_out, int out_size)
{
    const float* cnn  = (const float*)d_in[0];
    const float* gaz  = (const float*)d_in[1];
    const float* gazb = (const float*)d_in[2];
    const float* gm   = (const float*)d_in[3];
    const float* expi = (const float*)d_in[4];
    const float* Wcat = (const float*)d_in[5];
    const float* bcat = (const float*)d_in[6];
    const float* Wexp = (const float*)d_in[7];
    const float* bexp = (const float*)d_in[8];
    float* out = (float*)d_out;

    wprep<<<9216, 256>>>(cnn, gaz, gazb, gm, expi, Wcat, Wexp);

    cudaFuncSetAttribute(layergate_mma,
                         cudaFuncAttributeMaxDynamicSharedMemorySize, SMEM_TOTAL);
    layergate_mma<<<dim3(4, 128, 4), 256, SMEM_TOTAL>>>(cnn, expi, bcat, bexp, out);
}

// round 17
// speedup vs baseline: 1.0108x; 1.0108x over previous
#include <cuda_runtime.h>
#include <cuda_fp16.h>
#include <cstdint>
#include <math.h>

// LayerGate as one GEMM D[65536,512] = X[65536,512] @ W_aug[512,512] (per j-block),
// fp16 single-pass mma.sync.m16n8k16 (fp32 acc), fused gate epilogue.
// A fragments pre-packed in MMA register order -> register-direct LDG.128 (no A smem).
// B: per-warpgroup 3-stage cp.async rings with NAMED barriers (bar.sync id,128) --
// the two wn-halves touch disjoint B rows, so the CTA-wide barrier is removed and
// the two warpgroup pipelines run fully decoupled. 2 CTAs/SM (<=128 regs).
// Weight columns reordered n' = h*4 + g.

namespace {
constexpr int RING_BYTES  = 49152;   // per warpgroup: 3 stages x 16KB (K=128 B-half)
constexpr int SMEM_TOTAL  = 98304;   // 2 rings (front 64KB reused as gate tile)
}

// A fragment planes: [rowblk][kblk 8][lane 32][16B], 16B = one thread's a0..a3
__device__ __align__(16) unsigned char g_fa0[4096ull * 8 * 32 * 16]; // CNN (rows 65536)
__device__ __align__(16) unsigned char g_fgf[1024ull * 8 * 32 * 16]; // gaz  (rows 16384)
__device__ __align__(16) unsigned char g_fgb[1024ull * 8 * 32 * 16]; // gazb
__device__ __align__(16) unsigned char g_fgm[1024ull * 8 * 32 * 16]; // gm
__device__ __align__(16) unsigned char g_fex[1024ull * 8 * 32 * 16]; // exp
// [j][n'][k] fp16, n'=512 reordered cols = 2MB
__device__ __align__(16) unsigned char g_wh[4ull * 512 * 1024];

// ---------- PTX helpers (compute_80-level; safe under .target sm_103) ----------
__device__ __forceinline__ uint32_t smem_u32(const void* p) {
    uint32_t a;
    asm("{ .reg .u64 t; cvta.to.shared.u64 t, %1; cvt.u32.u64 %0, t; }" : "=r"(a) : "l"(p));
    return a;
}
__device__ __forceinline__ void cp16(uint32_t dst, const void* src) {
    asm volatile("cp.async.cg.shared.global [%0], [%1], 16;" :: "r"(dst), "l"(src));
}
__device__ __forceinline__ void cp_commit() {
    asm volatile("cp.async.commit_group;" ::: "memory");
}
__device__ __forceinline__ void cp_wait1() {
    asm volatile("cp.async.wait_group 1;" ::: "memory");
}
__device__ __forceinline__ void barsync(int id) {
    asm volatile("bar.sync %0, 128;" :: "r"(id) : "memory");
}
__device__ __forceinline__ void ldsm4(uint32_t* r, uint32_t addr) {
    asm volatile("ldmatrix.sync.aligned.m8n8.x4.shared.b16 {%0,%1,%2,%3}, [%4];"
                 : "=r"(r[0]), "=r"(r[1]), "=r"(r[2]), "=r"(r[3]) : "r"(addr));
}
__device__ __forceinline__ void mma_fp16(float* d, const uint32_t* a, const uint32_t* b) {
    asm volatile("mma.sync.aligned.m16n8k16.row.col.f32.f16.f16.f32 "
                 "{%0,%1,%2,%3}, {%4,%5,%6,%7}, {%8,%9}, {%0,%1,%2,%3};"
                 : "+f"(d[0]), "+f"(d[1]), "+f"(d[2]), "+f"(d[3])
                 : "r"(a[0]), "r"(a[1]), "r"(a[2]), "r"(a[3]), "r"(b[0]), "r"(b[1]));
}
__device__ __forceinline__ uint32_t h2u(__half2 h) { return *reinterpret_cast<uint32_t*>(&h); }

// ---------- Prep: A fragment planes + weights, one launch ----------
// blocks [0,8192): A fragments (CNN then gaz/gazb/gm/exp); [8192,9216): weights
__global__ void __launch_bounds__(256) wprep(const float* __restrict__ cnn,
                                             const float* __restrict__ gaz,
                                             const float* __restrict__ gazb,
                                             const float* __restrict__ gm,
                                             const float* __restrict__ expi,
                                             const float* __restrict__ Wcat,
                                             const float* __restrict__ Wexp)
{
    const int bx = blockIdx.x;
    if (bx < 8192) {
        int idx = bx * 256 + threadIdx.x;          // 2,097,152 fragment-16B writers
        int lane = idx & 31;
        int kblk = (idx >> 5) & 7;
        const float* srcrow0;                      // fp32 row r0 base (stride 128 floats)
        unsigned char* dstp;
        if (idx < 1048576) {                       // CNN: 4096 rowblks
            int rowblk = idx >> 8;
            int r0 = rowblk * 16 + (lane >> 2);
            int j = r0 >> 14, b = (r0 >> 9) & 31, s = r0 & 511;
            srcrow0 = cnn + ((size_t)(b * 2048 + j * 512 + s) << 7);
            dstp = g_fa0 + ((size_t)(rowblk * 8 + kblk) * 32 + lane) * 16;
        } else {                                   // shared planes: 1024 rowblks each
            int idx2 = idx - 1048576;
            int p = idx2 >> 18;
            int rowblk = (idx2 & 262143) >> 8;
            int rr0 = rowblk * 16 + (lane >> 2);
            const float* base = (p == 0) ? gaz : (p == 1) ? gazb : (p == 2) ? gm : expi;
            unsigned char* pl  = (p == 0) ? g_fgf : (p == 1) ? g_fgb : (p == 2) ? g_fgm : g_fex;
            srcrow0 = base + ((size_t)rr0 << 7);
            dstp = pl + ((size_t)(rowblk * 8 + kblk) * 32 + lane) * 16;
        }
        int c0 = kblk * 16 + 2 * (lane & 3);
        float2 v00 = *reinterpret_cast<const float2*>(srcrow0 + c0);            // (r0,   c0)
        float2 v10 = *reinterpret_cast<const float2*>(srcrow0 + (8 << 7) + c0); // (r0+8, c0)
        float2 v01 = *reinterpret_cast<const float2*>(srcrow0 + c0 + 8);        // (r0,   c0+8)
        float2 v11 = *reinterpret_cast<const float2*>(srcrow0 + (8 << 7) + c0 + 8);
        uint4 o = make_uint4(h2u(__floats2half2_rn(v00.x, v00.y)),   // a0
                             h2u(__floats2half2_rn(v10.x, v10.y)),   // a1
                             h2u(__floats2half2_rn(v01.x, v01.y)),   // a2
                             h2u(__floats2half2_rn(v11.x, v11.y)));  // a3
        *reinterpret_cast<uint4*>(dstp) = o;
    } else {
        // weights -> g_wh, columns reordered n' = h*4+g
        int idx = (bx - 8192) * 256 + threadIdx.x;
        int h = idx & 127;
        int k = (idx >> 7) & 511;
        int j = idx >> 16;
#pragma unroll
        for (int g = 0; g < 4; g++) {
            float v;
            if (k < 384)     v = Wcat[(size_t)k * 2048 + j * 512 + g * 128 + h];
            else if (g >= 1) v = Wexp[(size_t)(k - 384) * 1536 + j * 384 + (g - 1) * 128 + h];
            else             v = 0.f;
            int npr = h * 4 + g;
            *reinterpret_cast<__half*>(g_wh + ((size_t)(j * 512) + npr) * 1024 + k * 2) =
                __float2half_rn(v);
        }
    }
}

// ---------- Main: register-direct A + per-warpgroup B rings + fused epilogue ----------
__global__ void __launch_bounds__(256, 2)
layergate_mma(const float* __restrict__ cnn,
              const float* __restrict__ expi,
              const float* __restrict__ bcat,
              const float* __restrict__ bexp,
              float* __restrict__ out)
{
    extern __shared__ __align__(1024) unsigned char smem[];
    const uint32_t sbase = smem_u32(smem);
    const int tid  = threadIdx.x;
    const int lane = tid & 31;
    const int wid  = tid >> 5;
    const int wm   = wid & 3;     // 4 warps in M (32 rows each)
    const int wn   = wid >> 2;    // warpgroup: 0 -> n'[0,64), 1 -> n'[64,128)
    const int gt   = tid & 127;   // thread id within warpgroup
    const int nt   = blockIdx.x;  // 0..3   (h-block of 32)
    const int mx   = blockIdx.y;  // 0..127 (128-row tile within j)
    const int j    = blockIdx.z;  // 0..3
    const int rbase = j * 16384 + mx * 128;
    const int b    = mx >> 2;           // batch of this tile
    const int s0   = (mx & 3) * 128;    // sequence offset of row 0

    const uint32_t gbase = sbase + wn * RING_BYTES;   // this warpgroup's B ring

    // A fragment base pointers per k-chunk sel (this thread's wm & lane baked in)
    const unsigned char* fbase[4];
    {
        int rb0 = (rbase >> 4) + wm * 2;
        fbase[0] = g_fa0 + ((size_t)(rb0 * 8) * 32 + lane) * 16;
        int rs0 = ((b * 512 + s0) >> 4) + wm * 2;
        size_t off = ((size_t)(rs0 * 8) * 32 + lane) * 16;
        fbase[1] = ((j & 1) ? g_fgb : g_fgf) + off;
        fbase[2] = g_fgm + off;
        fbase[3] = g_fex + off;
    }

    float acc[2][8][4];
#pragma unroll
    for (int mf = 0; mf < 2; mf++)
#pragma unroll
        for (int nf = 0; nf < 8; nf++)
#pragma unroll
            for (int c = 0; c < 4; c++) acc[mf][nf][c] = 0.f;

    uint32_t Ar[3][2][4];   // A fragment ring (3 kb deep)
    auto ldgA = [&](int kb, int slot) {
        const unsigned char* p = fbase[kb >> 3] + (kb & 7) * 512;
#pragma unroll
        for (int mf = 0; mf < 2; mf++) {
            uint4 v = *reinterpret_cast<const uint4*>(p + mf * 4096);
            Ar[slot][mf][0] = v.x; Ar[slot][mf][1] = v.y;
            Ar[slot][mf][2] = v.z; Ar[slot][mf][3] = v.w;
        }
    };

    // ---- per-warpgroup B stage loader: 1024 chunks (2 x 8KB subtiles), 8 cp16/thread
    auto issue_stage = [&](int s) {
        const uint32_t dst = gbase + (s % 3) * 16384;
#pragma unroll
        for (int i = 0; i < 8; i++) {
            int c = i * 128 + gt;                  // 1024 chunks of this B-half
            int sub = c >> 9;
            int r = (c >> 3) & 63, ch = c & 7;
            const unsigned char* src =
                g_wh + ((size_t)(j * 512) + nt * 128 + wn * 64 + r) * 1024
                     + (s * 2 + sub) * 128 + ch * 16;
            cp16(dst + sub * 8192 + r * 128 + ((ch ^ (r & 7)) * 16), src);
        }
        cp_commit();
    };

    // ldmatrix lane geometry (B only; rows are warpgroup-local 0..63)
    const int brow = (lane & 7) | ((lane >> 4) << 3);
    const int bc   = (lane >> 3) & 1;

    ldgA(0, 0); ldgA(1, 1); ldgA(2, 2);
    issue_stage(0);
    issue_stage(1);

#pragma unroll
    for (int s = 0; s < 4; s++) {
        cp_wait1();                      // this thread's stage s landed (s+1 may fly)
        barsync(1 + wn);                 // warpgroup-only convergence
        if (s + 2 < 4) issue_stage(s + 2);
        else           cp_commit();      // empty group keeps wait arithmetic exact
        const uint32_t st = gbase + (s % 3) * 16384;
        const uint32_t bRow = st + brow * 128;
#pragma unroll
        for (int kbl = 0; kbl < 8; kbl++) {
            const int kb = s * 8 + kbl;
            const int slot = kb % 3;
            const uint32_t bBase = bRow + (kbl >> 2) * 8192;
            const uint32_t boff = ((((kbl & 3) * 2) + bc) ^ (brow & 7)) * 16;
            uint32_t B[8][2];
#pragma unroll
            for (int ng = 0; ng < 4; ng++) {
                uint32_t t[4];
                ldsm4(t, bBase + ng * 2048 + boff);
                B[2 * ng][0] = t[0]; B[2 * ng][1] = t[1];
                B[2 * ng + 1][0] = t[2]; B[2 * ng + 1][1] = t[3];
            }
#pragma unroll
            for (int mf = 0; mf < 2; mf++)
#pragma unroll
                for (int nf = 0; nf < 8; nf++)
                    mma_fp16(acc[mf][nf], Ar[slot][mf], B[nf]);
            if (kb + 3 < 32) ldgA(kb + 3, slot);   // refill ring slot just freed
        }
    }

    // ---- Epilogue phase 1: dump acc to smem gate tile [128 rows][128 n'] fp32
    __syncthreads();                     // full-CTA: both rings dead, reuse as gate
    float* gate = reinterpret_cast<float*>(smem);
    const int gid = lane >> 2, tig = lane & 3;
#pragma unroll
    for (int mf = 0; mf < 2; mf++)
#pragma unroll
        for (int nf = 0; nf < 8; nf++) {
            int row = wm * 32 + mf * 16 + gid;
            int col = wn * 64 + nf * 8 + tig * 2;
            *reinterpret_cast<float2*>(gate + row * 128 + col) =
                make_float2(acc[mf][nf][0], acc[mf][nf][1]);
            *reinterpret_cast<float2*>(gate + (row + 8) * 128 + col) =
                make_float2(acc[mf][nf][2], acc[mf][nf][3]);
        }
    __syncthreads();

    // ---- Epilogue phase 2: per (row, h) gather float4 {ns,g1,g2,g3}, finish, store
    const int hl = lane;
    const int hg = nt * 32 + hl;
    const float bc0 = bcat[j * 512 + hg];
    const float bc1 = bcat[j * 512 + 128 + hg];
    const float bc2 = bcat[j * 512 + 256 + hg];
    const float bc3 = bcat[j * 512 + 384 + hg];
    const float be1 = bexp[j * 384 + hg];
    const float be2 = bexp[j * 384 + 128 + hg];
    const float be3 = bexp[j * 384 + 256 + hg];
#pragma unroll
    for (int i = 0; i < 16; i++) {
        const int row = wid * 16 + i;
        const int srow = s0 + row;
        float4 gv = *reinterpret_cast<const float4*>(gate + row * 128 + hl * 4);
        float s1 = cnn[((size_t)(b * 2048 + j * 512 + srow) << 7) + hg];
        float s2 = expi[((size_t)(b * 512 + srow) << 7) + hg];
        float ns = tanhf(gv.x + bc0);
        float g1 = 1.f / (1.f + __expf(-(gv.y + bc1 + be1)));
        float g2 = 1.f / (1.f + __expf(-(gv.z + bc2 + be2)));
        float g3 = 1.f / (1.f + __expf(-(gv.w + bc3 + be3)));
        float e1 = __expf(g1), e2 = __expf(g2), e3 = __expf(g3);
        float inv = 1.f / (e1 + e2 + e3);
        out[((size_t)(rbase + row) << 7) + hg] = (e1 * ns + e2 * s1 + e3 * s2) * inv;
    }
}

extern "C" void kernel_launch(void* const* d_in, const int* in_sizes, int n_in,
                              void* d_out, int out_size)
{
    const float* cnn  = (const float*)d_in[0];
    const float* gaz  = (const float*)d_in[1];
    const float* gazb = (const float*)d_in[2];
    const float* gm   = (const float*)d_in[3];
    const float* expi = (const float*)d_in[4];
    const float* Wcat = (const float*)d_in[5];
    const float* bcat = (const float*)d_in[6];
    const float* Wexp = (const float*)d_in[7];
    const float* bexp = (const float*)d_in[8];
    float* out = (float*)d_out;

    wprep<<<9216, 256>>>(cnn, gaz, gazb, gm, expi, Wcat, Wexp);

    cudaFuncSetAttribute(layergate_mma,
                         cudaFuncAttributeMaxDynamicSharedMemorySize, SMEM_TOTAL);
    layergate_mma<<<dim3(4, 128, 4), 256, SMEM_TOTAL>>>(cnn, expi, bcat, bexp, out);
}